// round 5
// baseline (speedup 1.0000x reference)
#include <cuda_runtime.h>
#include <cstdint>
#include <math.h>

#define BB 16
#define SS 1024
#define DD 768
#define HH 12
#define DHH 64
#define NROWS (BB*SS)   // 16384

// Scratch: Q/K in [B,H,S,DH]; V stored TRANSPOSED [B,H,DH,S] with token-perm
__device__ float g_Q[BB*HH*SS*DHH];
__device__ float g_K[BB*HH*SS*DHH];
__device__ float g_V[BB*HH*SS*DHH];

// ---------------------------------------------------------------------------
// helpers
// ---------------------------------------------------------------------------
__device__ __forceinline__ uint32_t f2tf32(float x) {
    uint32_t t;
    asm("cvt.rna.tf32.f32 %0, %1;" : "=r"(t) : "f"(x));
    return t;
}

// D = A*B + D,  m16n8k8, tf32 inputs, fp32 accum
__device__ __forceinline__ void mma_tf32(float c[4],
                                         uint32_t a0, uint32_t a1, uint32_t a2, uint32_t a3,
                                         uint32_t b0, uint32_t b1) {
    asm volatile(
        "mma.sync.aligned.m16n8k8.row.col.f32.tf32.tf32.f32 "
        "{%0,%1,%2,%3}, {%4,%5,%6,%7}, {%8,%9}, {%0,%1,%2,%3};"
        : "+f"(c[0]), "+f"(c[1]), "+f"(c[2]), "+f"(c[3])
        : "r"(a0), "r"(a1), "r"(a2), "r"(a3), "r"(b0), "r"(b1));
}

// perm within 8-group: pairs (t, t+4) -> (2i, 2i+1)
__device__ __forceinline__ int perm8(int t) { return ((t & 3) << 1) | (t >> 2); }

// ===========================================================================
// Kernel 1: QKV projection, C[n,m] = sum_k X[n,k] W[m,k] + b[m]
// 128x128 tile, BK=32, 256 threads (8 warps: 2m x 4n), warp tile 64x32.
// smem k-columns stored with perm8 -> all fragment loads are LDS.64.
// which==2 (V): operands swapped (A=W, B=X) so output is V^T [b,h,d,s]
// written with token-perm pre-applied (coalesced at 32B-sector level).
// ===========================================================================
#define QKV_STRIDE 36
__global__ __launch_bounds__(256) void qkv_mma_kernel(
    const float* __restrict__ X,
    const float* __restrict__ Wq, const float* __restrict__ bq,
    const float* __restrict__ Wk, const float* __restrict__ bk,
    const float* __restrict__ Wv, const float* __restrict__ bv)
{
    __shared__ uint32_t As[128 * QKV_STRIDE];
    __shared__ uint32_t Bs[128 * QKV_STRIDE];

    const int which = blockIdx.z;
    const float* W    = (which == 0) ? Wq : (which == 1) ? Wk : Wv;
    const float* bias = (which == 0) ? bq : (which == 1) ? bk : bv;
    float* out        = (which == 0) ? g_Q : (which == 1) ? g_K : g_V;

    const int tid = threadIdx.x;
    const int wid = tid >> 5;
    const int lane = tid & 31;
    const int g   = lane >> 2;     // groupID
    const int tig = lane & 3;      // threadID in group
    const int wm = wid >> 2;       // 0..1
    const int wn = wid & 3;        // 0..3
    const int n0 = blockIdx.y * 128;   // token tile
    const int m0 = blockIdx.x * 128;   // W-row tile

    // For V: swap roles so accumulator rows = W rows (d), cols = tokens.
    const float* srcA = (which == 2) ? (W + (size_t)m0 * DD) : (X + (size_t)n0 * DD);
    const float* srcB = (which == 2) ? (X + (size_t)n0 * DD) : (W + (size_t)m0 * DD);

    float acc[4][4][4];
    #pragma unroll
    for (int mt = 0; mt < 4; mt++)
        #pragma unroll
        for (int nt = 0; nt < 4; nt++)
            #pragma unroll
            for (int r = 0; r < 4; r++) acc[mt][nt][r] = 0.0f;

    // prefetch registers: per l, two float2 per matrix (d and d+4)
    float2 aLo[4], aHi[4], bLo[4], bHi[4];
    #pragma unroll
    for (int l = 0; l < 4; l++) {
        int idx = tid + l * 256;
        int row = idx >> 3;
        int sub = idx & 7;
        int g8 = (sub >> 1) << 3;
        int f  = sub & 1;
        const float* pa = srcA + (size_t)row * DD + g8 + 2 * f;
        const float* pb = srcB + (size_t)row * DD + g8 + 2 * f;
        aLo[l] = *(const float2*)pa;  aHi[l] = *(const float2*)(pa + 4);
        bLo[l] = *(const float2*)pb;  bHi[l] = *(const float2*)(pb + 4);
    }

    for (int s = 0; s < DD / 32; s++) {
        // store current stage to smem (tf32, perm8 layout: uint4 at g8+4f)
        #pragma unroll
        for (int l = 0; l < 4; l++) {
            int idx = tid + l * 256;
            int row = idx >> 3;
            int sub = idx & 7;
            int g8 = (sub >> 1) << 3;
            int f  = sub & 1;
            uint4 at = make_uint4(f2tf32(aLo[l].x), f2tf32(aHi[l].x),
                                  f2tf32(aLo[l].y), f2tf32(aHi[l].y));
            uint4 bt = make_uint4(f2tf32(bLo[l].x), f2tf32(bHi[l].x),
                                  f2tf32(bLo[l].y), f2tf32(bHi[l].y));
            *(uint4*)&As[row * QKV_STRIDE + g8 + 4 * f] = at;
            *(uint4*)&Bs[row * QKV_STRIDE + g8 + 4 * f] = bt;
        }
        __syncthreads();

        // prefetch next stage
        if (s + 1 < DD / 32) {
            const int k0 = (s + 1) * 32;
            #pragma unroll
            for (int l = 0; l < 4; l++) {
                int idx = tid + l * 256;
                int row = idx >> 3;
                int sub = idx & 7;
                int g8 = (sub >> 1) << 3;
                int f  = sub & 1;
                const float* pa = srcA + (size_t)row * DD + k0 + g8 + 2 * f;
                const float* pb = srcB + (size_t)row * DD + k0 + g8 + 2 * f;
                aLo[l] = *(const float2*)pa;  aHi[l] = *(const float2*)(pa + 4);
                bLo[l] = *(const float2*)pb;  bHi[l] = *(const float2*)(pb + 4);
            }
        }

        // 4 k-steps of 8; all fragment loads LDS.64
        #pragma unroll
        for (int ks = 0; ks < 4; ks++) {
            const int kk = ks * 8 + 2 * tig;
            uint2 bb[4];
            #pragma unroll
            for (int nt = 0; nt < 4; nt++) {
                int col = wn * 32 + nt * 8 + g;
                bb[nt] = *(const uint2*)&Bs[col * QKV_STRIDE + kk];
            }
            #pragma unroll
            for (int mt = 0; mt < 4; mt++) {
                int row = wm * 64 + mt * 16 + g;
                uint2 A0 = *(const uint2*)&As[row * QKV_STRIDE + kk];
                uint2 A1 = *(const uint2*)&As[(row + 8) * QKV_STRIDE + kk];
                #pragma unroll
                for (int nt = 0; nt < 4; nt++)
                    mma_tf32(acc[mt][nt], A0.x, A1.x, A0.y, A1.y, bb[nt].x, bb[nt].y);
            }
        }
        __syncthreads();
    }

    if (which < 2) {
        // epilogue Q/K: bias + scatter to [B,H,S,DH]
        #pragma unroll
        for (int mt = 0; mt < 4; mt++) {
            #pragma unroll
            for (int half = 0; half < 2; half++) {
                int n = n0 + wm * 64 + mt * 16 + g + half * 8;
                int b_idx = n >> 10;
                int s_idx = n & 1023;
                #pragma unroll
                for (int nt = 0; nt < 4; nt++) {
                    int col = m0 + wn * 32 + nt * 8 + 2 * tig;
                    int h = col >> 6, d = col & 63;
                    float2 v;
                    v.x = acc[mt][nt][half * 2 + 0] + bias[col];
                    v.y = acc[mt][nt][half * 2 + 1] + bias[col + 1];
                    *(float2*)(out + (((size_t)b_idx * HH + h) * SS + s_idx) * DHH + d) = v;
                }
            }
        }
    } else {
        // epilogue V: rows = d, cols = tokens; write V^T[b,h,d,s'] token-permuted
        const int pc0 = perm8(2 * tig);
        const int pc1 = perm8(2 * tig + 1);
        #pragma unroll
        for (int mt = 0; mt < 4; mt++) {
            #pragma unroll
            for (int half = 0; half < 2; half++) {
                int dglob = m0 + wm * 64 + mt * 16 + g + half * 8;
                int h = dglob >> 6, d = dglob & 63;
                float bi = bias[dglob];
                #pragma unroll
                for (int nt = 0; nt < 4; nt++) {
                    int n = n0 + wn * 32 + nt * 8;   // token group base (mult of 8)
                    int b_idx = n >> 10;
                    int sgrp = n & 1023;
                    size_t base = ((size_t)(b_idx * HH + h) * DHH + d) * SS + sgrp;
                    out[base + pc0] = acc[mt][nt][half * 2 + 0] + bi;
                    out[base + pc1] = acc[mt][nt][half * 2 + 1] + bi;
                }
            }
        }
    }
}

// ===========================================================================
// Kernel 2: flash attention with tf32 mma.sync + LDS.64 fragment loads.
// Block: one (b,h), q-tile 128 rows. 256 threads = 8 warps x 16 q-rows.
// Q/K smem d-permuted; P smem token-permuted; V^T already permuted in gmem.
// ===========================================================================
#define AT_STRIDE 68
#define Q_OFF 0
#define K_OFF (128 * AT_STRIDE)
#define V_OFF (K_OFF + 64 * AT_STRIDE)
#define P_OFF (V_OFF + 64 * AT_STRIDE)
#define AT_SMEM_FLOATS (P_OFF + 128 * AT_STRIDE)
#define AT_SMEM_BYTES (AT_SMEM_FLOATS * 4)   // 104448

__global__ __launch_bounds__(256) void attn_mma_kernel(float* __restrict__ out)
{
    extern __shared__ uint32_t sm[];
    uint32_t* Qs = sm + Q_OFF;
    uint32_t* Ks = sm + K_OFF;
    uint32_t* Vt = sm + V_OFF;   // [d][tok'] (token-permuted)
    uint32_t* Ps = sm + P_OFF;   // [q][tok'] (token-permuted)

    const int tid = threadIdx.x;
    const int wid = tid >> 5;
    const int lane = tid & 31;
    const int g   = lane >> 2;
    const int tig = lane & 3;
    const int bh = blockIdx.y;
    const int q0 = blockIdx.x * 128;
    const int b  = bh / HH;
    const int h  = bh % HH;

    const float* Qg  = g_Q + (size_t)bh * SS * DHH + (size_t)q0 * DHH;
    const float* Kg  = g_K + (size_t)bh * SS * DHH;
    const float* VTg = g_V + (size_t)bh * DHH * SS;   // [d][s'] layout

    // load Q tile (128 x 64) -> tf32 smem, d-perm via pair-load trick
    #pragma unroll
    for (int l = 0; l < 8; l++) {
        int idx = tid + l * 256;
        int row = idx >> 4;
        int sub = idx & 15;
        int g8 = (sub >> 1) << 3;
        int f  = sub & 1;
        const float* p = Qg + (size_t)row * DHH + g8 + 2 * f;
        float2 a = *(const float2*)p;
        float2 c = *(const float2*)(p + 4);
        uint4 t = make_uint4(f2tf32(a.x), f2tf32(c.x), f2tf32(a.y), f2tf32(c.y));
        *(uint4*)&Qs[row * AT_STRIDE + g8 + 4 * f] = t;
    }

    float o[8][4];
    float m_i[2], l_i[2];
    #pragma unroll
    for (int nt = 0; nt < 8; nt++)
        #pragma unroll
        for (int r = 0; r < 4; r++) o[nt][r] = 0.0f;
    m_i[0] = m_i[1] = -1e30f;
    l_i[0] = l_i[1] = 0.0f;

    const int arow = wid * 16 + g;          // this thread's base q-row
    const int pc0 = perm8(2 * tig);
    const int pc1 = perm8(2 * tig + 1);
    const float scale = 0.125f;

    for (int kt = 0; kt < 16; kt++) {
        __syncthreads();   // prev PV done reading Vt/Ps; covers Q load at kt=0

        // K tile (64 x 64), d-perm pair-load
        const float* Kt = Kg + (size_t)kt * 64 * DHH;
        #pragma unroll
        for (int l = 0; l < 4; l++) {
            int idx = tid + l * 256;
            int row = idx >> 4;
            int sub = idx & 15;
            int g8 = (sub >> 1) << 3;
            int f  = sub & 1;
            const float* p = Kt + (size_t)row * DHH + g8 + 2 * f;
            float2 a = *(const float2*)p;
            float2 c = *(const float2*)(p + 4);
            uint4 t = make_uint4(f2tf32(a.x), f2tf32(c.x), f2tf32(a.y), f2tf32(c.y));
            *(uint4*)&Ks[row * AT_STRIDE + g8 + 4 * f] = t;
        }
        // V^T tile (64 d-rows x 64 tokens): straight copy (perm already in gmem)
        #pragma unroll
        for (int l = 0; l < 4; l++) {
            int idx = tid + l * 256;
            int row = idx >> 4;          // d index
            int c4  = (idx & 15) * 4;    // token offset
            float4 v = *(const float4*)(VTg + (size_t)row * SS + kt * 64 + c4);
            uint4 t = make_uint4(f2tf32(v.x), f2tf32(v.y), f2tf32(v.z), f2tf32(v.w));
            *(uint4*)&Vt[row * AT_STRIDE + c4] = t;
        }
        __syncthreads();

        // --- S = Q @ K^T (warp: 16 x 64) ---
        float sfr[8][4];
        #pragma unroll
        for (int nt = 0; nt < 8; nt++)
            #pragma unroll
            for (int r = 0; r < 4; r++) sfr[nt][r] = 0.0f;

        #pragma unroll
        for (int ks = 0; ks < 8; ks++) {
            const int kk = ks * 8 + 2 * tig;
            uint2 A0 = *(const uint2*)&Qs[arow * AT_STRIDE + kk];
            uint2 A1 = *(const uint2*)&Qs[(arow + 8) * AT_STRIDE + kk];
            #pragma unroll
            for (int nt = 0; nt < 8; nt++) {
                int tok = nt * 8 + g;
                uint2 bb = *(const uint2*)&Ks[tok * AT_STRIDE + kk];
                mma_tf32(sfr[nt], A0.x, A1.x, A0.y, A1.y, bb.x, bb.y);
            }
        }

        // --- online softmax (rows arow and arow+8) ---
        #pragma unroll
        for (int half = 0; half < 2; half++) {
            float mx = -1e30f;
            #pragma unroll
            for (int nt = 0; nt < 8; nt++) {
                sfr[nt][half * 2 + 0] *= scale;
                sfr[nt][half * 2 + 1] *= scale;
                mx = fmaxf(mx, fmaxf(sfr[nt][half * 2], sfr[nt][half * 2 + 1]));
            }
            mx = fmaxf(mx, __shfl_xor_sync(0xffffffffu, mx, 1));
            mx = fmaxf(mx, __shfl_xor_sync(0xffffffffu, mx, 2));

            float mnew  = fmaxf(m_i[half], mx);
            float alpha = __expf(m_i[half] - mnew);
            m_i[half] = mnew;

            float rsum = 0.0f;
            #pragma unroll
            for (int nt = 0; nt < 8; nt++) {
                float p0 = __expf(sfr[nt][half * 2 + 0] - mnew);
                float p1 = __expf(sfr[nt][half * 2 + 1] - mnew);
                sfr[nt][half * 2 + 0] = p0;
                sfr[nt][half * 2 + 1] = p1;
                rsum += p0 + p1;
            }
            rsum += __shfl_xor_sync(0xffffffffu, rsum, 1);
            rsum += __shfl_xor_sync(0xffffffffu, rsum, 2);

            l_i[half] = l_i[half] * alpha + rsum;
            #pragma unroll
            for (int nt = 0; nt < 8; nt++) {
                o[nt][half * 2 + 0] *= alpha;
                o[nt][half * 2 + 1] *= alpha;
            }
        }

        // --- store P (tf32) token-permuted; warp-local rows only ---
        #pragma unroll
        for (int nt = 0; nt < 8; nt++) {
            int base0 = arow * AT_STRIDE + nt * 8;
            int base1 = (arow + 8) * AT_STRIDE + nt * 8;
            Ps[base0 + pc0] = f2tf32(sfr[nt][0]);
            Ps[base0 + pc1] = f2tf32(sfr[nt][1]);
            Ps[base1 + pc0] = f2tf32(sfr[nt][2]);
            Ps[base1 + pc1] = f2tf32(sfr[nt][3]);
        }
        __syncwarp();   // each warp reads only its own P rows

        // --- O += P @ V (k-dim = 64 tokens, all LDS.64) ---
        #pragma unroll
        for (int ks = 0; ks < 8; ks++) {
            const int kk = ks * 8 + 2 * tig;
            uint2 A0 = *(const uint2*)&Ps[arow * AT_STRIDE + kk];
            uint2 A1 = *(const uint2*)&Ps[(arow + 8) * AT_STRIDE + kk];
            #pragma unroll
            for (int nt = 0; nt < 8; nt++) {
                int dcol = nt * 8 + g;
                uint2 bb = *(const uint2*)&Vt[dcol * AT_STRIDE + kk];
                mma_tf32(o[nt], A0.x, A1.x, A0.y, A1.y, bb.x, bb.y);
            }
        }
    }

    // --- finalize: normalize + write out[b, s, h*64+d] ---
    #pragma unroll
    for (int half = 0; half < 2; half++) {
        float inv = 1.0f / l_i[half];
        int srow = q0 + arow + half * 8;
        float* dst = out + ((size_t)b * SS + srow) * DD + h * DHH;
        #pragma unroll
        for (int nt = 0; nt < 8; nt++) {
            int d = nt * 8 + 2 * tig;
            float2 v = make_float2(o[nt][half * 2] * inv, o[nt][half * 2 + 1] * inv);
            *(float2*)(dst + d) = v;
        }
    }
}

// ---------------------------------------------------------------------------
extern "C" void kernel_launch(void* const* d_in, const int* in_sizes, int n_in,
                              void* d_out, int out_size)
{
    const float* X  = (const float*)d_in[0];
    const float* Wq = (const float*)d_in[1];
    const float* bq = (const float*)d_in[2];
    const float* Wk = (const float*)d_in[3];
    const float* bk = (const float*)d_in[4];
    const float* Wv = (const float*)d_in[5];
    const float* bv = (const float*)d_in[6];
    float* out = (float*)d_out;

    cudaFuncSetAttribute(attn_mma_kernel,
                         cudaFuncAttributeMaxDynamicSharedMemorySize, AT_SMEM_BYTES);

    dim3 g1(DD / 128, NROWS / 128, 3);   // (6, 128, 3)
    qkv_mma_kernel<<<g1, 256>>>(X, Wq, bq, Wk, bk, Wv, bv);

    dim3 g2(SS / 128, BB * HH);          // (8, 192)
    attn_mma_kernel<<<g2, 256, AT_SMEM_BYTES>>>(out);
}

// round 6
// speedup vs baseline: 1.9582x; 1.9582x over previous
#include <cuda_runtime.h>
#include <cuda_fp16.h>
#include <cstdint>
#include <math.h>

#define BB 16
#define SS 1024
#define DD 768
#define HH 12
#define DHH 64
#define NROWS (BB*SS)   // 16384

// Scratch: Q/K/V in [B,H,S,DH] layout (head-major, DH contiguous)
__device__ float g_Q[BB*HH*SS*DHH];
__device__ float g_K[BB*HH*SS*DHH];
__device__ float g_V[BB*HH*SS*DHH];

// ---------------------------------------------------------------------------
// helpers
// ---------------------------------------------------------------------------
__device__ __forceinline__ uint32_t f2tf32(float x) {
    uint32_t t;
    asm("cvt.rna.tf32.f32 %0, %1;" : "=r"(t) : "f"(x));
    return t;
}

// D = A*B + D,  m16n8k8, tf32 inputs, fp32 accum
__device__ __forceinline__ void mma_tf32(float c[4],
                                         uint32_t a0, uint32_t a1, uint32_t a2, uint32_t a3,
                                         uint32_t b0, uint32_t b1) {
    asm volatile(
        "mma.sync.aligned.m16n8k8.row.col.f32.tf32.tf32.f32 "
        "{%0,%1,%2,%3}, {%4,%5,%6,%7}, {%8,%9}, {%0,%1,%2,%3};"
        : "+f"(c[0]), "+f"(c[1]), "+f"(c[2]), "+f"(c[3])
        : "r"(a0), "r"(a1), "r"(a2), "r"(a3), "r"(b0), "r"(b1));
}

// D = A*B + D,  m16n8k16, fp16 inputs, fp32 accum
__device__ __forceinline__ void mma_f16(float c[4],
                                        uint32_t a0, uint32_t a1, uint32_t a2, uint32_t a3,
                                        uint32_t b0, uint32_t b1) {
    asm volatile(
        "mma.sync.aligned.m16n8k16.row.col.f32.f16.f16.f32 "
        "{%0,%1,%2,%3}, {%4,%5,%6,%7}, {%8,%9}, {%0,%1,%2,%3};"
        : "+f"(c[0]), "+f"(c[1]), "+f"(c[2]), "+f"(c[3])
        : "r"(a0), "r"(a1), "r"(a2), "r"(a3), "r"(b0), "r"(b1));
}

#define LDSM_X4(r0, r1, r2, r3, addr) \
    asm volatile("ldmatrix.sync.aligned.m8n8.x4.shared.b16 {%0,%1,%2,%3}, [%4];" \
        : "=r"(r0), "=r"(r1), "=r"(r2), "=r"(r3) : "r"(addr))

#define LDSM_X4_T(r0, r1, r2, r3, addr) \
    asm volatile("ldmatrix.sync.aligned.m8n8.x4.trans.shared.b16 {%0,%1,%2,%3}, [%4];" \
        : "=r"(r0), "=r"(r1), "=r"(r2), "=r"(r3) : "r"(addr))

__device__ __forceinline__ uint32_t pack_h2(float lo, float hi) {
    half2 h = __floats2half2_rn(lo, hi);
    return *reinterpret_cast<uint32_t*>(&h);
}

// ===========================================================================
// Kernel 1: QKV projection (tf32, exact R4 version — known 397us).
// C[n,m] = sum_k X[n,k] W[m,k] + b[m]. 128x128 tile, BK=32, 8 warps.
// ===========================================================================
#define QKV_STRIDE 36
__global__ __launch_bounds__(256) void qkv_mma_kernel(
    const float* __restrict__ X,
    const float* __restrict__ Wq, const float* __restrict__ bq,
    const float* __restrict__ Wk, const float* __restrict__ bk,
    const float* __restrict__ Wv, const float* __restrict__ bv)
{
    __shared__ uint32_t As[128 * QKV_STRIDE];
    __shared__ uint32_t Bs[128 * QKV_STRIDE];

    const int which = blockIdx.z;
    const float* W    = (which == 0) ? Wq : (which == 1) ? Wk : Wv;
    const float* bias = (which == 0) ? bq : (which == 1) ? bk : bv;
    float* out        = (which == 0) ? g_Q : (which == 1) ? g_K : g_V;

    const int tid = threadIdx.x;
    const int wid = tid >> 5;
    const int lane = tid & 31;
    const int g   = lane >> 2;
    const int tig = lane & 3;
    const int wm = wid >> 2;
    const int wn = wid & 3;
    const int n0 = blockIdx.y * 128;
    const int m0 = blockIdx.x * 128;

    const float* srcA = X + (size_t)n0 * DD;
    const float* srcB = W + (size_t)m0 * DD;

    float acc[4][4][4];
    #pragma unroll
    for (int mt = 0; mt < 4; mt++)
        #pragma unroll
        for (int nt = 0; nt < 4; nt++)
            #pragma unroll
            for (int r = 0; r < 4; r++) acc[mt][nt][r] = 0.0f;

    float4 ra[4], rb[4];
    #pragma unroll
    for (int l = 0; l < 4; l++) {
        int idx = tid + l * 256;
        int row = idx >> 3, c4 = (idx & 7) * 4;
        ra[l] = *(const float4*)(srcA + (size_t)row * DD + c4);
        rb[l] = *(const float4*)(srcB + (size_t)row * DD + c4);
    }

    for (int s = 0; s < DD / 32; s++) {
        #pragma unroll
        for (int l = 0; l < 4; l++) {
            int idx = tid + l * 256;
            int row = idx >> 3, c4 = (idx & 7) * 4;
            uint4 at = make_uint4(f2tf32(ra[l].x), f2tf32(ra[l].y),
                                  f2tf32(ra[l].z), f2tf32(ra[l].w));
            uint4 bt = make_uint4(f2tf32(rb[l].x), f2tf32(rb[l].y),
                                  f2tf32(rb[l].z), f2tf32(rb[l].w));
            *(uint4*)&As[row * QKV_STRIDE + c4] = at;
            *(uint4*)&Bs[row * QKV_STRIDE + c4] = bt;
        }
        __syncthreads();

        if (s + 1 < DD / 32) {
            const int k0 = (s + 1) * 32;
            #pragma unroll
            for (int l = 0; l < 4; l++) {
                int idx = tid + l * 256;
                int row = idx >> 3, c4 = (idx & 7) * 4;
                ra[l] = *(const float4*)(srcA + (size_t)row * DD + k0 + c4);
                rb[l] = *(const float4*)(srcB + (size_t)row * DD + k0 + c4);
            }
        }

        #pragma unroll
        for (int ks = 0; ks < 4; ks++) {
            const int kc = ks * 8 + tig;
            uint32_t bf[4][2];
            #pragma unroll
            for (int nt = 0; nt < 4; nt++) {
                int col = wn * 32 + nt * 8 + g;
                bf[nt][0] = Bs[col * QKV_STRIDE + kc];
                bf[nt][1] = Bs[col * QKV_STRIDE + kc + 4];
            }
            #pragma unroll
            for (int mt = 0; mt < 4; mt++) {
                int row = wm * 64 + mt * 16 + g;
                uint32_t a0 = As[row * QKV_STRIDE + kc];
                uint32_t a1 = As[(row + 8) * QKV_STRIDE + kc];
                uint32_t a2 = As[row * QKV_STRIDE + kc + 4];
                uint32_t a3 = As[(row + 8) * QKV_STRIDE + kc + 4];
                #pragma unroll
                for (int nt = 0; nt < 4; nt++)
                    mma_tf32(acc[mt][nt], a0, a1, a2, a3, bf[nt][0], bf[nt][1]);
            }
        }
        __syncthreads();
    }

    #pragma unroll
    for (int mt = 0; mt < 4; mt++) {
        #pragma unroll
        for (int half = 0; half < 2; half++) {
            int n = n0 + wm * 64 + mt * 16 + g + half * 8;
            int b_idx = n >> 10;
            int s_idx = n & 1023;
            #pragma unroll
            for (int nt = 0; nt < 4; nt++) {
                int col = m0 + wn * 32 + nt * 8 + 2 * tig;
                int h = col >> 6, d = col & 63;
                float2 v;
                v.x = acc[mt][nt][half * 2 + 0] + bias[col];
                v.y = acc[mt][nt][half * 2 + 1] + bias[col + 1];
                *(float2*)(out + (((size_t)b_idx * HH + h) * SS + s_idx) * DHH + d) = v;
            }
        }
    }
}

// ===========================================================================
// Kernel 2: flash attention, fp16 m16n8k16 + ldmatrix, P kept in registers.
// Block: one (b,h), q-tile 128 rows, 8 warps x 16 q-rows.
// smem: Q 128x72 halves, K 64x72, V 64x72 (row stride 72 -> conflict-free).
// ===========================================================================
#define AT_H 72   // halves per row

__global__ __launch_bounds__(256) void attn_mma_kernel(float* __restrict__ out)
{
    __shared__ __half Qs[128 * AT_H];
    __shared__ __half Ks[64 * AT_H];
    __shared__ __half Vs[64 * AT_H];

    const int tid = threadIdx.x;
    const int wid = tid >> 5;
    const int lane = tid & 31;
    const int tig = lane & 3;
    const int bh = blockIdx.y;
    const int q0 = blockIdx.x * 128;
    const int b  = bh / HH;
    const int h  = bh % HH;

    const float* Qg = g_Q + (size_t)bh * SS * DHH + (size_t)q0 * DHH;
    const float* Kg = g_K + (size_t)bh * SS * DHH;
    const float* Vg = g_V + (size_t)bh * SS * DHH;

    // ldmatrix lane decomposition: matrix m = lane>>3, row r = lane&7
    const int lm = lane >> 3;
    const int lr = lane & 7;

    // per-thread ldmatrix row/col offsets (halves)
    // A (Q): row = wid*16 + (m&1)*8 + r ; col = ks*16 + (m>>1)*8
    const int qa_row = wid * 16 + (lm & 1) * 8 + lr;
    const int qa_col = (lm >> 1) * 8;
    // B (K): row(token) = ntp*16 + (m>>1)*8 + r ; col = ks*16 + (m&1)*8
    const int kb_row = (lm >> 1) * 8 + lr;
    const int kb_col = (lm & 1) * 8;
    // B (V, trans): row(token) = ks*16 + (m&1)*8 + r ; col(d) = dp*16 + (m>>1)*8
    const int vb_row = (lm & 1) * 8 + lr;
    const int vb_col = (lm >> 1) * 8;

    uint32_t qs_base = (uint32_t)__cvta_generic_to_shared(Qs);
    uint32_t ks_base = (uint32_t)__cvta_generic_to_shared(Ks);
    uint32_t vs_base = (uint32_t)__cvta_generic_to_shared(Vs);

    const uint32_t qa_addr0 = qs_base + (qa_row * AT_H + qa_col) * 2;
    const uint32_t kb_addr0 = ks_base + (kb_row * AT_H + kb_col) * 2;
    const uint32_t vb_addr0 = vs_base + (vb_row * AT_H + vb_col) * 2;

    // load Q tile (128 x 64 fp32 -> fp16 smem): 1024 items of 8 floats
    #pragma unroll
    for (int l = 0; l < 4; l++) {
        int idx = tid + l * 256;
        int row = idx >> 3, c8 = (idx & 7) * 8;
        const float* p = Qg + (size_t)row * DHH + c8;
        float4 f0 = *(const float4*)p;
        float4 f1 = *(const float4*)(p + 4);
        uint4 t = make_uint4(pack_h2(f0.x, f0.y), pack_h2(f0.z, f0.w),
                             pack_h2(f1.x, f1.y), pack_h2(f1.z, f1.w));
        *(uint4*)&Qs[row * AT_H + c8] = t;
    }

    float o[8][4];
    float m_i[2], l_i[2];
    #pragma unroll
    for (int nt = 0; nt < 8; nt++)
        #pragma unroll
        for (int r = 0; r < 4; r++) o[nt][r] = 0.0f;
    m_i[0] = m_i[1] = -1e30f;
    l_i[0] = l_i[1] = 0.0f;

    const float scale = 0.125f;

    for (int kt = 0; kt < 16; kt++) {
        __syncthreads();   // prev tile's MMAs done reading Ks/Vs; covers Q at kt=0

        // load K,V tiles (64 x 64 each): 512 items of 8 floats each
        const float* Kt = Kg + (size_t)kt * 64 * DHH;
        const float* Vt = Vg + (size_t)kt * 64 * DHH;
        #pragma unroll
        for (int l = 0; l < 2; l++) {
            int idx = tid + l * 256;
            int row = idx >> 3, c8 = (idx & 7) * 8;
            const float* pk = Kt + (size_t)row * DHH + c8;
            const float* pv = Vt + (size_t)row * DHH + c8;
            float4 k0 = *(const float4*)pk;
            float4 k1 = *(const float4*)(pk + 4);
            float4 v0 = *(const float4*)pv;
            float4 v1 = *(const float4*)(pv + 4);
            uint4 tk = make_uint4(pack_h2(k0.x, k0.y), pack_h2(k0.z, k0.w),
                                  pack_h2(k1.x, k1.y), pack_h2(k1.z, k1.w));
            uint4 tv = make_uint4(pack_h2(v0.x, v0.y), pack_h2(v0.z, v0.w),
                                  pack_h2(v1.x, v1.y), pack_h2(v1.z, v1.w));
            *(uint4*)&Ks[row * AT_H + c8] = tk;
            *(uint4*)&Vs[row * AT_H + c8] = tv;
        }
        __syncthreads();

        // --- S = Q @ K^T (warp: 16 x 64), k-dim 64 in 4 steps of 16 ---
        float sfr[8][4];
        #pragma unroll
        for (int nt = 0; nt < 8; nt++)
            #pragma unroll
            for (int r = 0; r < 4; r++) sfr[nt][r] = 0.0f;

        #pragma unroll
        for (int ks = 0; ks < 4; ks++) {
            uint32_t a0, a1, a2, a3;
            LDSM_X4(a0, a1, a2, a3, qa_addr0 + ks * 16 * 2);
            #pragma unroll
            for (int ntp = 0; ntp < 4; ntp++) {
                uint32_t b0, b1, b2, b3;
                LDSM_X4(b0, b1, b2, b3,
                        kb_addr0 + (ntp * 16 * AT_H + ks * 16) * 2);
                mma_f16(sfr[2 * ntp + 0], a0, a1, a2, a3, b0, b1);
                mma_f16(sfr[2 * ntp + 1], a0, a1, a2, a3, b2, b3);
            }
        }

        // --- online softmax (rows arow and arow+8) ---
        #pragma unroll
        for (int half = 0; half < 2; half++) {
            float mx = -1e30f;
            #pragma unroll
            for (int nt = 0; nt < 8; nt++) {
                sfr[nt][half * 2 + 0] *= scale;
                sfr[nt][half * 2 + 1] *= scale;
                mx = fmaxf(mx, fmaxf(sfr[nt][half * 2], sfr[nt][half * 2 + 1]));
            }
            mx = fmaxf(mx, __shfl_xor_sync(0xffffffffu, mx, 1));
            mx = fmaxf(mx, __shfl_xor_sync(0xffffffffu, mx, 2));

            float mnew  = fmaxf(m_i[half], mx);
            float alpha = __expf(m_i[half] - mnew);
            m_i[half] = mnew;

            float rsum = 0.0f;
            #pragma unroll
            for (int nt = 0; nt < 8; nt++) {
                float p0 = __expf(sfr[nt][half * 2 + 0] - mnew);
                float p1 = __expf(sfr[nt][half * 2 + 1] - mnew);
                sfr[nt][half * 2 + 0] = p0;
                sfr[nt][half * 2 + 1] = p1;
                rsum += p0 + p1;
            }
            rsum += __shfl_xor_sync(0xffffffffu, rsum, 1);
            rsum += __shfl_xor_sync(0xffffffffu, rsum, 2);

            l_i[half] = l_i[half] * alpha + rsum;
            #pragma unroll
            for (int nt = 0; nt < 8; nt++) {
                o[nt][half * 2 + 0] *= alpha;
                o[nt][half * 2 + 1] *= alpha;
            }
        }

        // --- O += P @ V : P a-frags come straight from sfr registers ---
        #pragma unroll
        for (int ks = 0; ks < 4; ks++) {
            uint32_t a0 = pack_h2(sfr[2 * ks][0],     sfr[2 * ks][1]);
            uint32_t a1 = pack_h2(sfr[2 * ks][2],     sfr[2 * ks][3]);
            uint32_t a2 = pack_h2(sfr[2 * ks + 1][0], sfr[2 * ks + 1][1]);
            uint32_t a3 = pack_h2(sfr[2 * ks + 1][2], sfr[2 * ks + 1][3]);
            #pragma unroll
            for (int dp = 0; dp < 4; dp++) {
                uint32_t b0, b1, b2, b3;
                LDSM_X4_T(b0, b1, b2, b3,
                          vb_addr0 + (ks * 16 * AT_H + dp * 16) * 2);
                mma_f16(o[2 * dp + 0], a0, a1, a2, a3, b0, b1);
                mma_f16(o[2 * dp + 1], a0, a1, a2, a3, b2, b3);
            }
        }
    }

    // --- finalize: normalize + write out[b, s, h*64+d] ---
    const int arow = wid * 16 + (lane >> 2);
    #pragma unroll
    for (int half = 0; half < 2; half++) {
        float inv = 1.0f / l_i[half];
        int srow = q0 + arow + half * 8;
        float* dst = out + ((size_t)b * SS + srow) * DD + h * DHH;
        #pragma unroll
        for (int nt = 0; nt < 8; nt++) {
            int d = nt * 8 + 2 * tig;
            float2 v = make_float2(o[nt][half * 2] * inv, o[nt][half * 2 + 1] * inv);
            *(float2*)(dst + d) = v;
        }
    }
}

// ---------------------------------------------------------------------------
extern "C" void kernel_launch(void* const* d_in, const int* in_sizes, int n_in,
                              void* d_out, int out_size)
{
    const float* X  = (const float*)d_in[0];
    const float* Wq = (const float*)d_in[1];
    const float* bq = (const float*)d_in[2];
    const float* Wk = (const float*)d_in[3];
    const float* bk = (const float*)d_in[4];
    const float* Wv = (const float*)d_in[5];
    const float* bv = (const float*)d_in[6];
    float* out = (float*)d_out;

    dim3 g1(DD / 128, NROWS / 128, 3);   // (6, 128, 3)
    qkv_mma_kernel<<<g1, 256>>>(X, Wq, bq, Wk, bk, Wv, bv);

    dim3 g2(SS / 128, BB * HH);          // (8, 192)
    attn_mma_kernel<<<g2, 256>>>(out);
}

// round 7
// speedup vs baseline: 2.0587x; 1.0513x over previous
#include <cuda_runtime.h>
#include <cuda_fp16.h>
#include <cstdint>
#include <math.h>

#define BB 16
#define SS 1024
#define DD 768
#define HH 12
#define DHH 64
#define NROWS (BB*SS)   // 16384

// Scratch: Q/K/V in [B,H,S,DH] layout (head-major, DH contiguous)
__device__ float g_Q[BB*HH*SS*DHH];
__device__ float g_K[BB*HH*SS*DHH];
__device__ float g_V[BB*HH*SS*DHH];

// ---------------------------------------------------------------------------
// helpers
// ---------------------------------------------------------------------------
__device__ __forceinline__ uint32_t f2tf32(float x) {
    uint32_t t;
    asm("cvt.rna.tf32.f32 %0, %1;" : "=r"(t) : "f"(x));
    return t;
}

// D = A*B + D,  m16n8k8, tf32 inputs, fp32 accum
__device__ __forceinline__ void mma_tf32(float c[4],
                                         uint32_t a0, uint32_t a1, uint32_t a2, uint32_t a3,
                                         uint32_t b0, uint32_t b1) {
    asm volatile(
        "mma.sync.aligned.m16n8k8.row.col.f32.tf32.tf32.f32 "
        "{%0,%1,%2,%3}, {%4,%5,%6,%7}, {%8,%9}, {%0,%1,%2,%3};"
        : "+f"(c[0]), "+f"(c[1]), "+f"(c[2]), "+f"(c[3])
        : "r"(a0), "r"(a1), "r"(a2), "r"(a3), "r"(b0), "r"(b1));
}

// D = A*B + D,  m16n8k16, fp16 inputs, fp32 accum
__device__ __forceinline__ void mma_f16(float c[4],
                                        uint32_t a0, uint32_t a1, uint32_t a2, uint32_t a3,
                                        uint32_t b0, uint32_t b1) {
    asm volatile(
        "mma.sync.aligned.m16n8k16.row.col.f32.f16.f16.f32 "
        "{%0,%1,%2,%3}, {%4,%5,%6,%7}, {%8,%9}, {%0,%1,%2,%3};"
        : "+f"(c[0]), "+f"(c[1]), "+f"(c[2]), "+f"(c[3])
        : "r"(a0), "r"(a1), "r"(a2), "r"(a3), "r"(b0), "r"(b1));
}

#define LDSM_X4(r0, r1, r2, r3, addr) \
    asm volatile("ldmatrix.sync.aligned.m8n8.x4.shared.b16 {%0,%1,%2,%3}, [%4];" \
        : "=r"(r0), "=r"(r1), "=r"(r2), "=r"(r3) : "r"(addr))

#define LDSM_X4_T(r0, r1, r2, r3, addr) \
    asm volatile("ldmatrix.sync.aligned.m8n8.x4.trans.shared.b16 {%0,%1,%2,%3}, [%4];" \
        : "=r"(r0), "=r"(r1), "=r"(r2), "=r"(r3) : "r"(addr))

__device__ __forceinline__ uint32_t pack_h2(float lo, float hi) {
    half2 h = __floats2half2_rn(lo, hi);
    return *reinterpret_cast<uint32_t*>(&h);
}

// ===========================================================================
// Kernel 1: QKV projection (tf32) with ldmatrix fragment loads.
// C[n,m] = sum_k X[n,k] W[m,k] + b[m]. 128x128 tile, BK=32, 8 warps (2m x 4n),
// warp tile 64x32. tf32 8x8 tile == 8x16 b16 tile -> ldmatrix.x4 delivers
// a0..a3 (A) and {b0,b1} x 2 n-tiles (B) in mma operand order.
// stride 36 words: ldmatrix rows hit banks 4r+col -> conflict-free.
// ===========================================================================
#define QKV_STRIDE 36
__global__ __launch_bounds__(256) void qkv_mma_kernel(
    const float* __restrict__ X,
    const float* __restrict__ Wq, const float* __restrict__ bq,
    const float* __restrict__ Wk, const float* __restrict__ bk,
    const float* __restrict__ Wv, const float* __restrict__ bv)
{
    __shared__ uint32_t As[128 * QKV_STRIDE];
    __shared__ uint32_t Bs[128 * QKV_STRIDE];

    const int which = blockIdx.z;
    const float* W    = (which == 0) ? Wq : (which == 1) ? Wk : Wv;
    const float* bias = (which == 0) ? bq : (which == 1) ? bk : bv;
    float* out        = (which == 0) ? g_Q : (which == 1) ? g_K : g_V;

    const int tid = threadIdx.x;
    const int wid = tid >> 5;
    const int lane = tid & 31;
    const int g   = lane >> 2;
    const int tig = lane & 3;
    const int wm = wid >> 2;
    const int wn = wid & 3;
    const int n0 = blockIdx.y * 128;
    const int m0 = blockIdx.x * 128;

    const float* srcA = X + (size_t)n0 * DD;
    const float* srcB = W + (size_t)m0 * DD;

    // ldmatrix per-lane addressing (quad = lane>>3, r = lane&7)
    const int quad = lane >> 3;
    const int lr   = lane & 7;
    const int a_row = (quad & 1) * 8 + lr;      // + mt*16 within warp A tile
    const int a_col = (quad >> 1) * 4;          // + ks*8
    const int b_row = (quad >> 1) * 8 + lr;     // + ntp*16 within warp B tile
    const int b_col = (quad & 1) * 4;           // + ks*8

    const uint32_t as_base = (uint32_t)__cvta_generic_to_shared(As);
    const uint32_t bs_base = (uint32_t)__cvta_generic_to_shared(Bs);
    const uint32_t a_addr0 = as_base + ((wm * 64 + a_row) * QKV_STRIDE + a_col) * 4;
    const uint32_t b_addr0 = bs_base + ((wn * 32 + b_row) * QKV_STRIDE + b_col) * 4;

    float acc[4][4][4];
    #pragma unroll
    for (int mt = 0; mt < 4; mt++)
        #pragma unroll
        for (int nt = 0; nt < 4; nt++)
            #pragma unroll
            for (int r = 0; r < 4; r++) acc[mt][nt][r] = 0.0f;

    float4 ra[4], rb[4];
    #pragma unroll
    for (int l = 0; l < 4; l++) {
        int idx = tid + l * 256;
        int row = idx >> 3, c4 = (idx & 7) * 4;
        ra[l] = *(const float4*)(srcA + (size_t)row * DD + c4);
        rb[l] = *(const float4*)(srcB + (size_t)row * DD + c4);
    }

    for (int s = 0; s < DD / 32; s++) {
        #pragma unroll
        for (int l = 0; l < 4; l++) {
            int idx = tid + l * 256;
            int row = idx >> 3, c4 = (idx & 7) * 4;
            uint4 at = make_uint4(f2tf32(ra[l].x), f2tf32(ra[l].y),
                                  f2tf32(ra[l].z), f2tf32(ra[l].w));
            uint4 bt = make_uint4(f2tf32(rb[l].x), f2tf32(rb[l].y),
                                  f2tf32(rb[l].z), f2tf32(rb[l].w));
            *(uint4*)&As[row * QKV_STRIDE + c4] = at;
            *(uint4*)&Bs[row * QKV_STRIDE + c4] = bt;
        }
        __syncthreads();

        if (s + 1 < DD / 32) {
            const int k0 = (s + 1) * 32;
            #pragma unroll
            for (int l = 0; l < 4; l++) {
                int idx = tid + l * 256;
                int row = idx >> 3, c4 = (idx & 7) * 4;
                ra[l] = *(const float4*)(srcA + (size_t)row * DD + k0 + c4);
                rb[l] = *(const float4*)(srcB + (size_t)row * DD + k0 + c4);
            }
        }

        // 4 k-steps of 8; fragment loads via ldmatrix.x4
        #pragma unroll
        for (int ks = 0; ks < 4; ks++) {
            uint32_t bf[2][4];
            #pragma unroll
            for (int ntp = 0; ntp < 2; ntp++) {
                LDSM_X4(bf[ntp][0], bf[ntp][1], bf[ntp][2], bf[ntp][3],
                        b_addr0 + (ntp * 16 * QKV_STRIDE + ks * 8) * 4);
            }
            #pragma unroll
            for (int mt = 0; mt < 4; mt++) {
                uint32_t a0, a1, a2, a3;
                LDSM_X4(a0, a1, a2, a3,
                        a_addr0 + (mt * 16 * QKV_STRIDE + ks * 8) * 4);
                #pragma unroll
                for (int ntp = 0; ntp < 2; ntp++) {
                    mma_tf32(acc[mt][2 * ntp + 0], a0, a1, a2, a3,
                             bf[ntp][0], bf[ntp][1]);
                    mma_tf32(acc[mt][2 * ntp + 1], a0, a1, a2, a3,
                             bf[ntp][2], bf[ntp][3]);
                }
            }
        }
        __syncthreads();
    }

    #pragma unroll
    for (int mt = 0; mt < 4; mt++) {
        #pragma unroll
        for (int half = 0; half < 2; half++) {
            int n = n0 + wm * 64 + mt * 16 + g + half * 8;
            int b_idx = n >> 10;
            int s_idx = n & 1023;
            #pragma unroll
            for (int nt = 0; nt < 4; nt++) {
                int col = m0 + wn * 32 + nt * 8 + 2 * tig;
                int h = col >> 6, d = col & 63;
                float2 v;
                v.x = acc[mt][nt][half * 2 + 0] + bias[col];
                v.y = acc[mt][nt][half * 2 + 1] + bias[col + 1];
                *(float2*)(out + (((size_t)b_idx * HH + h) * SS + s_idx) * DHH + d) = v;
            }
        }
    }
}

// ===========================================================================
// Kernel 2: flash attention, fp16 m16n8k16 + ldmatrix, P kept in registers.
// (unchanged from R6 — 244us, protect the win)
// ===========================================================================
#define AT_H 72   // halves per row

__global__ __launch_bounds__(256) void attn_mma_kernel(float* __restrict__ out)
{
    __shared__ __half Qs[128 * AT_H];
    __shared__ __half Ks[64 * AT_H];
    __shared__ __half Vs[64 * AT_H];

    const int tid = threadIdx.x;
    const int wid = tid >> 5;
    const int lane = tid & 31;
    const int tig = lane & 3;
    const int bh = blockIdx.y;
    const int q0 = blockIdx.x * 128;
    const int b  = bh / HH;
    const int h  = bh % HH;

    const float* Qg = g_Q + (size_t)bh * SS * DHH + (size_t)q0 * DHH;
    const float* Kg = g_K + (size_t)bh * SS * DHH;
    const float* Vg = g_V + (size_t)bh * SS * DHH;

    const int lm = lane >> 3;
    const int lr = lane & 7;

    const int qa_row = wid * 16 + (lm & 1) * 8 + lr;
    const int qa_col = (lm >> 1) * 8;
    const int kb_row = (lm >> 1) * 8 + lr;
    const int kb_col = (lm & 1) * 8;
    const int vb_row = (lm & 1) * 8 + lr;
    const int vb_col = (lm >> 1) * 8;

    uint32_t qs_base = (uint32_t)__cvta_generic_to_shared(Qs);
    uint32_t ks_base = (uint32_t)__cvta_generic_to_shared(Ks);
    uint32_t vs_base = (uint32_t)__cvta_generic_to_shared(Vs);

    const uint32_t qa_addr0 = qs_base + (qa_row * AT_H + qa_col) * 2;
    const uint32_t kb_addr0 = ks_base + (kb_row * AT_H + kb_col) * 2;
    const uint32_t vb_addr0 = vs_base + (vb_row * AT_H + vb_col) * 2;

    #pragma unroll
    for (int l = 0; l < 4; l++) {
        int idx = tid + l * 256;
        int row = idx >> 3, c8 = (idx & 7) * 8;
        const float* p = Qg + (size_t)row * DHH + c8;
        float4 f0 = *(const float4*)p;
        float4 f1 = *(const float4*)(p + 4);
        uint4 t = make_uint4(pack_h2(f0.x, f0.y), pack_h2(f0.z, f0.w),
                             pack_h2(f1.x, f1.y), pack_h2(f1.z, f1.w));
        *(uint4*)&Qs[row * AT_H + c8] = t;
    }

    float o[8][4];
    float m_i[2], l_i[2];
    #pragma unroll
    for (int nt = 0; nt < 8; nt++)
        #pragma unroll
        for (int r = 0; r < 4; r++) o[nt][r] = 0.0f;
    m_i[0] = m_i[1] = -1e30f;
    l_i[0] = l_i[1] = 0.0f;

    const float scale = 0.125f;

    for (int kt = 0; kt < 16; kt++) {
        __syncthreads();

        const float* Kt = Kg + (size_t)kt * 64 * DHH;
        const float* Vt = Vg + (size_t)kt * 64 * DHH;
        #pragma unroll
        for (int l = 0; l < 2; l++) {
            int idx = tid + l * 256;
            int row = idx >> 3, c8 = (idx & 7) * 8;
            const float* pk = Kt + (size_t)row * DHH + c8;
            const float* pv = Vt + (size_t)row * DHH + c8;
            float4 k0 = *(const float4*)pk;
            float4 k1 = *(const float4*)(pk + 4);
            float4 v0 = *(const float4*)pv;
            float4 v1 = *(const float4*)(pv + 4);
            uint4 tk = make_uint4(pack_h2(k0.x, k0.y), pack_h2(k0.z, k0.w),
                                  pack_h2(k1.x, k1.y), pack_h2(k1.z, k1.w));
            uint4 tv = make_uint4(pack_h2(v0.x, v0.y), pack_h2(v0.z, v0.w),
                                  pack_h2(v1.x, v1.y), pack_h2(v1.z, v1.w));
            *(uint4*)&Ks[row * AT_H + c8] = tk;
            *(uint4*)&Vs[row * AT_H + c8] = tv;
        }
        __syncthreads();

        float sfr[8][4];
        #pragma unroll
        for (int nt = 0; nt < 8; nt++)
            #pragma unroll
            for (int r = 0; r < 4; r++) sfr[nt][r] = 0.0f;

        #pragma unroll
        for (int ks = 0; ks < 4; ks++) {
            uint32_t a0, a1, a2, a3;
            LDSM_X4(a0, a1, a2, a3, qa_addr0 + ks * 16 * 2);
            #pragma unroll
            for (int ntp = 0; ntp < 4; ntp++) {
                uint32_t b0, b1, b2, b3;
                LDSM_X4(b0, b1, b2, b3,
                        kb_addr0 + (ntp * 16 * AT_H + ks * 16) * 2);
                mma_f16(sfr[2 * ntp + 0], a0, a1, a2, a3, b0, b1);
                mma_f16(sfr[2 * ntp + 1], a0, a1, a2, a3, b2, b3);
            }
        }

        #pragma unroll
        for (int half = 0; half < 2; half++) {
            float mx = -1e30f;
            #pragma unroll
            for (int nt = 0; nt < 8; nt++) {
                sfr[nt][half * 2 + 0] *= scale;
                sfr[nt][half * 2 + 1] *= scale;
                mx = fmaxf(mx, fmaxf(sfr[nt][half * 2], sfr[nt][half * 2 + 1]));
            }
            mx = fmaxf(mx, __shfl_xor_sync(0xffffffffu, mx, 1));
            mx = fmaxf(mx, __shfl_xor_sync(0xffffffffu, mx, 2));

            float mnew  = fmaxf(m_i[half], mx);
            float alpha = __expf(m_i[half] - mnew);
            m_i[half] = mnew;

            float rsum = 0.0f;
            #pragma unroll
            for (int nt = 0; nt < 8; nt++) {
                float p0 = __expf(sfr[nt][half * 2 + 0] - mnew);
                float p1 = __expf(sfr[nt][half * 2 + 1] - mnew);
                sfr[nt][half * 2 + 0] = p0;
                sfr[nt][half * 2 + 1] = p1;
                rsum += p0 + p1;
            }
            rsum += __shfl_xor_sync(0xffffffffu, rsum, 1);
            rsum += __shfl_xor_sync(0xffffffffu, rsum, 2);

            l_i[half] = l_i[half] * alpha + rsum;
            #pragma unroll
            for (int nt = 0; nt < 8; nt++) {
                o[nt][half * 2 + 0] *= alpha;
                o[nt][half * 2 + 1] *= alpha;
            }
        }

        #pragma unroll
        for (int ks = 0; ks < 4; ks++) {
            uint32_t a0 = pack_h2(sfr[2 * ks][0],     sfr[2 * ks][1]);
            uint32_t a1 = pack_h2(sfr[2 * ks][2],     sfr[2 * ks][3]);
            uint32_t a2 = pack_h2(sfr[2 * ks + 1][0], sfr[2 * ks + 1][1]);
            uint32_t a3 = pack_h2(sfr[2 * ks + 1][2], sfr[2 * ks + 1][3]);
            #pragma unroll
            for (int dp = 0; dp < 4; dp++) {
                uint32_t b0, b1, b2, b3;
                LDSM_X4_T(b0, b1, b2, b3,
                          vb_addr0 + (ks * 16 * AT_H + dp * 16) * 2);
                mma_f16(o[2 * dp + 0], a0, a1, a2, a3, b0, b1);
                mma_f16(o[2 * dp + 1], a0, a1, a2, a3, b2, b3);
            }
        }
    }

    const int arow = wid * 16 + (lane >> 2);
    #pragma unroll
    for (int half = 0; half < 2; half++) {
        float inv = 1.0f / l_i[half];
        int srow = q0 + arow + half * 8;
        float* dst = out + ((size_t)b * SS + srow) * DD + h * DHH;
        #pragma unroll
        for (int nt = 0; nt < 8; nt++) {
            int d = nt * 8 + 2 * tig;
            float2 v = make_float2(o[nt][half * 2] * inv, o[nt][half * 2 + 1] * inv);
            *(float2*)(dst + d) = v;
        }
    }
}

// ---------------------------------------------------------------------------
extern "C" void kernel_launch(void* const* d_in, const int* in_sizes, int n_in,
                              void* d_out, int out_size)
{
    const float* X  = (const float*)d_in[0];
    const float* Wq = (const float*)d_in[1];
    const float* bq = (const float*)d_in[2];
    const float* Wk = (const float*)d_in[3];
    const float* bk = (const float*)d_in[4];
    const float* Wv = (const float*)d_in[5];
    const float* bv = (const float*)d_in[6];
    float* out = (float*)d_out;

    dim3 g1(DD / 128, NROWS / 128, 3);   // (6, 128, 3)
    qkv_mma_kernel<<<g1, 256>>>(X, Wq, bq, Wk, bk, Wv, bv);

    dim3 g2(SS / 128, BB * HH);          // (8, 192)
    attn_mma_kernel<<<g2, 256>>>(out);
}

// round 8
// speedup vs baseline: 2.4660x; 1.1978x over previous
#include <cuda_runtime.h>
#include <cuda_fp16.h>
#include <cstdint>
#include <math.h>

#define BB 16
#define SS 1024
#define DD 768
#define HH 12
#define DHH 64
#define NROWS (BB*SS)   // 16384

// Scratch: Q/K/V in [B,H,S,DH] layout (head-major, DH contiguous)
__device__ float g_Q[BB*HH*SS*DHH];
__device__ float g_K[BB*HH*SS*DHH];
__device__ float g_V[BB*HH*SS*DHH];

// ---------------------------------------------------------------------------
// helpers
// ---------------------------------------------------------------------------
// D = A*B + D,  m16n8k16, fp16 inputs, fp32 accum
__device__ __forceinline__ void mma_f16(float c[4],
                                        uint32_t a0, uint32_t a1, uint32_t a2, uint32_t a3,
                                        uint32_t b0, uint32_t b1) {
    asm volatile(
        "mma.sync.aligned.m16n8k16.row.col.f32.f16.f16.f32 "
        "{%0,%1,%2,%3}, {%4,%5,%6,%7}, {%8,%9}, {%0,%1,%2,%3};"
        : "+f"(c[0]), "+f"(c[1]), "+f"(c[2]), "+f"(c[3])
        : "r"(a0), "r"(a1), "r"(a2), "r"(a3), "r"(b0), "r"(b1));
}

#define LDSM_X4(r0, r1, r2, r3, addr) \
    asm volatile("ldmatrix.sync.aligned.m8n8.x4.shared.b16 {%0,%1,%2,%3}, [%4];" \
        : "=r"(r0), "=r"(r1), "=r"(r2), "=r"(r3) : "r"(addr))

#define LDSM_X4_T(r0, r1, r2, r3, addr) \
    asm volatile("ldmatrix.sync.aligned.m8n8.x4.trans.shared.b16 {%0,%1,%2,%3}, [%4];" \
        : "=r"(r0), "=r"(r1), "=r"(r2), "=r"(r3) : "r"(addr))

__device__ __forceinline__ uint32_t pack_h2(float lo, float hi) {
    half2 h = __floats2half2_rn(lo, hi);
    return *reinterpret_cast<uint32_t*>(&h);
}

// ===========================================================================
// Kernel 1: QKV projection (fp16 m16n8k16 + ldmatrix).
// C[n,m] = sum_k X[n,k] W[m,k] + b[m]. 128x128 tile, BK=32, 8 warps (2m x 4n),
// warp tile 64x32. smem rows: 32 data halves + 8 pad = stride 40 halves (80B):
// r*80 mod 128 covers all 32 banks -> ldmatrix conflict-free.
// ===========================================================================
#define QKV_H 40    // halves per smem row
__global__ __launch_bounds__(256) void qkv_mma_kernel(
    const float* __restrict__ X,
    const float* __restrict__ Wq, const float* __restrict__ bq,
    const float* __restrict__ Wk, const float* __restrict__ bk,
    const float* __restrict__ Wv, const float* __restrict__ bv)
{
    __shared__ __half As[128 * QKV_H];
    __shared__ __half Bs[128 * QKV_H];

    const int which = blockIdx.z;
    const float* W    = (which == 0) ? Wq : (which == 1) ? Wk : Wv;
    const float* bias = (which == 0) ? bq : (which == 1) ? bk : bv;
    float* out        = (which == 0) ? g_Q : (which == 1) ? g_K : g_V;

    const int tid = threadIdx.x;
    const int wid = tid >> 5;
    const int lane = tid & 31;
    const int g   = lane >> 2;
    const int tig = lane & 3;
    const int wm = wid >> 2;
    const int wn = wid & 3;
    const int n0 = blockIdx.y * 128;
    const int m0 = blockIdx.x * 128;

    const float* srcA = X + (size_t)n0 * DD;
    const float* srcB = W + (size_t)m0 * DD;

    // ldmatrix per-lane addressing (fp16 16x16 tiles; m = lane>>3, r = lane&7)
    const int lm = lane >> 3;
    const int lr = lane & 7;
    // A: row = wm*64 + mt*16 + (m&1)*8 + r ; col(halves) = ks*16 + (m>>1)*8
    const int a_row = (lm & 1) * 8 + lr;
    const int a_col = (lm >> 1) * 8;
    // B: row(col idx) = wn*32 + ntp*16 + (m>>1)*8 + r ; col = ks*16 + (m&1)*8
    const int b_row = (lm >> 1) * 8 + lr;
    const int b_col = (lm & 1) * 8;

    const uint32_t as_base = (uint32_t)__cvta_generic_to_shared(As);
    const uint32_t bs_base = (uint32_t)__cvta_generic_to_shared(Bs);
    const uint32_t a_addr0 = as_base + ((wm * 64 + a_row) * QKV_H + a_col) * 2;
    const uint32_t b_addr0 = bs_base + ((wn * 32 + b_row) * QKV_H + b_col) * 2;

    float acc[4][4][4];
    #pragma unroll
    for (int mt = 0; mt < 4; mt++)
        #pragma unroll
        for (int nt = 0; nt < 4; nt++)
            #pragma unroll
            for (int r = 0; r < 4; r++) acc[mt][nt][r] = 0.0f;

    // gmem prefetch: per stage each thread loads 8 floats of A and 8 of B
    // (128 rows x 32 k / 256 threads = 16 floats -> 2 items of 8)
    float4 ra0[2], ra1[2], rb0[2], rb1[2];
    #pragma unroll
    for (int l = 0; l < 2; l++) {
        int idx = tid + l * 256;
        int row = idx >> 2, c8 = (idx & 3) * 8;
        const float* pa = srcA + (size_t)row * DD + c8;
        const float* pb = srcB + (size_t)row * DD + c8;
        ra0[l] = *(const float4*)pa;  ra1[l] = *(const float4*)(pa + 4);
        rb0[l] = *(const float4*)pb;  rb1[l] = *(const float4*)(pb + 4);
    }

    for (int s = 0; s < DD / 32; s++) {
        // store current stage to smem (fp16)
        #pragma unroll
        for (int l = 0; l < 2; l++) {
            int idx = tid + l * 256;
            int row = idx >> 2, c8 = (idx & 3) * 8;
            uint4 at = make_uint4(pack_h2(ra0[l].x, ra0[l].y), pack_h2(ra0[l].z, ra0[l].w),
                                  pack_h2(ra1[l].x, ra1[l].y), pack_h2(ra1[l].z, ra1[l].w));
            uint4 bt = make_uint4(pack_h2(rb0[l].x, rb0[l].y), pack_h2(rb0[l].z, rb0[l].w),
                                  pack_h2(rb1[l].x, rb1[l].y), pack_h2(rb1[l].z, rb1[l].w));
            *(uint4*)&As[row * QKV_H + c8] = at;
            *(uint4*)&Bs[row * QKV_H + c8] = bt;
        }
        __syncthreads();

        // prefetch next stage
        if (s + 1 < DD / 32) {
            const int k0 = (s + 1) * 32;
            #pragma unroll
            for (int l = 0; l < 2; l++) {
                int idx = tid + l * 256;
                int row = idx >> 2, c8 = (idx & 3) * 8;
                const float* pa = srcA + (size_t)row * DD + k0 + c8;
                const float* pb = srcB + (size_t)row * DD + k0 + c8;
                ra0[l] = *(const float4*)pa;  ra1[l] = *(const float4*)(pa + 4);
                rb0[l] = *(const float4*)pb;  rb1[l] = *(const float4*)(pb + 4);
            }
        }

        // 2 k-steps of 16
        #pragma unroll
        for (int ks = 0; ks < 2; ks++) {
            uint32_t bf[2][4];
            #pragma unroll
            for (int ntp = 0; ntp < 2; ntp++) {
                LDSM_X4(bf[ntp][0], bf[ntp][1], bf[ntp][2], bf[ntp][3],
                        b_addr0 + (ntp * 16 * QKV_H + ks * 16) * 2);
            }
            #pragma unroll
            for (int mt = 0; mt < 4; mt++) {
                uint32_t a0, a1, a2, a3;
                LDSM_X4(a0, a1, a2, a3,
                        a_addr0 + (mt * 16 * QKV_H + ks * 16) * 2);
                #pragma unroll
                for (int ntp = 0; ntp < 2; ntp++) {
                    mma_f16(acc[mt][2 * ntp + 0], a0, a1, a2, a3,
                            bf[ntp][0], bf[ntp][1]);
                    mma_f16(acc[mt][2 * ntp + 1], a0, a1, a2, a3,
                            bf[ntp][2], bf[ntp][3]);
                }
            }
        }
        __syncthreads();
    }

    // epilogue: bias + scatter to [B,H,S,DH]
    #pragma unroll
    for (int mt = 0; mt < 4; mt++) {
        #pragma unroll
        for (int half = 0; half < 2; half++) {
            int n = n0 + wm * 64 + mt * 16 + g + half * 8;
            int b_idx = n >> 10;
            int s_idx = n & 1023;
            #pragma unroll
            for (int nt = 0; nt < 4; nt++) {
                int col = m0 + wn * 32 + nt * 8 + 2 * tig;
                int h = col >> 6, d = col & 63;
                float2 v;
                v.x = acc[mt][nt][half * 2 + 0] + bias[col];
                v.y = acc[mt][nt][half * 2 + 1] + bias[col + 1];
                *(float2*)(out + (((size_t)b_idx * HH + h) * SS + s_idx) * DHH + d) = v;
            }
        }
    }
}

// ===========================================================================
// Kernel 2: flash attention, fp16 m16n8k16 + ldmatrix, P kept in registers.
// (unchanged from R6 — 244us, protect the win)
// ===========================================================================
#define AT_H 72   // halves per row

__global__ __launch_bounds__(256) void attn_mma_kernel(float* __restrict__ out)
{
    __shared__ __half Qs[128 * AT_H];
    __shared__ __half Ks[64 * AT_H];
    __shared__ __half Vs[64 * AT_H];

    const int tid = threadIdx.x;
    const int wid = tid >> 5;
    const int lane = tid & 31;
    const int tig = lane & 3;
    const int bh = blockIdx.y;
    const int q0 = blockIdx.x * 128;
    const int b  = bh / HH;
    const int h  = bh % HH;

    const float* Qg = g_Q + (size_t)bh * SS * DHH + (size_t)q0 * DHH;
    const float* Kg = g_K + (size_t)bh * SS * DHH;
    const float* Vg = g_V + (size_t)bh * SS * DHH;

    const int lm = lane >> 3;
    const int lr = lane & 7;

    const int qa_row = wid * 16 + (lm & 1) * 8 + lr;
    const int qa_col = (lm >> 1) * 8;
    const int kb_row = (lm >> 1) * 8 + lr;
    const int kb_col = (lm & 1) * 8;
    const int vb_row = (lm & 1) * 8 + lr;
    const int vb_col = (lm >> 1) * 8;

    uint32_t qs_base = (uint32_t)__cvta_generic_to_shared(Qs);
    uint32_t ks_base = (uint32_t)__cvta_generic_to_shared(Ks);
    uint32_t vs_base = (uint32_t)__cvta_generic_to_shared(Vs);

    const uint32_t qa_addr0 = qs_base + (qa_row * AT_H + qa_col) * 2;
    const uint32_t kb_addr0 = ks_base + (kb_row * AT_H + kb_col) * 2;
    const uint32_t vb_addr0 = vs_base + (vb_row * AT_H + vb_col) * 2;

    #pragma unroll
    for (int l = 0; l < 4; l++) {
        int idx = tid + l * 256;
        int row = idx >> 3, c8 = (idx & 7) * 8;
        const float* p = Qg + (size_t)row * DHH + c8;
        float4 f0 = *(const float4*)p;
        float4 f1 = *(const float4*)(p + 4);
        uint4 t = make_uint4(pack_h2(f0.x, f0.y), pack_h2(f0.z, f0.w),
                             pack_h2(f1.x, f1.y), pack_h2(f1.z, f1.w));
        *(uint4*)&Qs[row * AT_H + c8] = t;
    }

    float o[8][4];
    float m_i[2], l_i[2];
    #pragma unroll
    for (int nt = 0; nt < 8; nt++)
        #pragma unroll
        for (int r = 0; r < 4; r++) o[nt][r] = 0.0f;
    m_i[0] = m_i[1] = -1e30f;
    l_i[0] = l_i[1] = 0.0f;

    const float scale = 0.125f;

    for (int kt = 0; kt < 16; kt++) {
        __syncthreads();

        const float* Kt = Kg + (size_t)kt * 64 * DHH;
        const float* Vt = Vg + (size_t)kt * 64 * DHH;
        #pragma unroll
        for (int l = 0; l < 2; l++) {
            int idx = tid + l * 256;
            int row = idx >> 3, c8 = (idx & 7) * 8;
            const float* pk = Kt + (size_t)row * DHH + c8;
            const float* pv = Vt + (size_t)row * DHH + c8;
            float4 k0 = *(const float4*)pk;
            float4 k1 = *(const float4*)(pk + 4);
            float4 v0 = *(const float4*)pv;
            float4 v1 = *(const float4*)(pv + 4);
            uint4 tk = make_uint4(pack_h2(k0.x, k0.y), pack_h2(k0.z, k0.w),
                                  pack_h2(k1.x, k1.y), pack_h2(k1.z, k1.w));
            uint4 tv = make_uint4(pack_h2(v0.x, v0.y), pack_h2(v0.z, v0.w),
                                  pack_h2(v1.x, v1.y), pack_h2(v1.z, v1.w));
            *(uint4*)&Ks[row * AT_H + c8] = tk;
            *(uint4*)&Vs[row * AT_H + c8] = tv;
        }
        __syncthreads();

        float sfr[8][4];
        #pragma unroll
        for (int nt = 0; nt < 8; nt++)
            #pragma unroll
            for (int r = 0; r < 4; r++) sfr[nt][r] = 0.0f;

        #pragma unroll
        for (int ks = 0; ks < 4; ks++) {
            uint32_t a0, a1, a2, a3;
            LDSM_X4(a0, a1, a2, a3, qa_addr0 + ks * 16 * 2);
            #pragma unroll
            for (int ntp = 0; ntp < 4; ntp++) {
                uint32_t b0, b1, b2, b3;
                LDSM_X4(b0, b1, b2, b3,
                        kb_addr0 + (ntp * 16 * AT_H + ks * 16) * 2);
                mma_f16(sfr[2 * ntp + 0], a0, a1, a2, a3, b0, b1);
                mma_f16(sfr[2 * ntp + 1], a0, a1, a2, a3, b2, b3);
            }
        }

        #pragma unroll
        for (int half = 0; half < 2; half++) {
            float mx = -1e30f;
            #pragma unroll
            for (int nt = 0; nt < 8; nt++) {
                sfr[nt][half * 2 + 0] *= scale;
                sfr[nt][half * 2 + 1] *= scale;
                mx = fmaxf(mx, fmaxf(sfr[nt][half * 2], sfr[nt][half * 2 + 1]));
            }
            mx = fmaxf(mx, __shfl_xor_sync(0xffffffffu, mx, 1));
            mx = fmaxf(mx, __shfl_xor_sync(0xffffffffu, mx, 2));

            float mnew  = fmaxf(m_i[half], mx);
            float alpha = __expf(m_i[half] - mnew);
            m_i[half] = mnew;

            float rsum = 0.0f;
            #pragma unroll
            for (int nt = 0; nt < 8; nt++) {
                float p0 = __expf(sfr[nt][half * 2 + 0] - mnew);
                float p1 = __expf(sfr[nt][half * 2 + 1] - mnew);
                sfr[nt][half * 2 + 0] = p0;
                sfr[nt][half * 2 + 1] = p1;
                rsum += p0 + p1;
            }
            rsum += __shfl_xor_sync(0xffffffffu, rsum, 1);
            rsum += __shfl_xor_sync(0xffffffffu, rsum, 2);

            l_i[half] = l_i[half] * alpha + rsum;
            #pragma unroll
            for (int nt = 0; nt < 8; nt++) {
                o[nt][half * 2 + 0] *= alpha;
                o[nt][half * 2 + 1] *= alpha;
            }
        }

        #pragma unroll
        for (int ks = 0; ks < 4; ks++) {
            uint32_t a0 = pack_h2(sfr[2 * ks][0],     sfr[2 * ks][1]);
            uint32_t a1 = pack_h2(sfr[2 * ks][2],     sfr[2 * ks][3]);
            uint32_t a2 = pack_h2(sfr[2 * ks + 1][0], sfr[2 * ks + 1][1]);
            uint32_t a3 = pack_h2(sfr[2 * ks + 1][2], sfr[2 * ks + 1][3]);
            #pragma unroll
            for (int dp = 0; dp < 4; dp++) {
                uint32_t b0, b1, b2, b3;
                LDSM_X4_T(b0, b1, b2, b3,
                          vb_addr0 + (ks * 16 * AT_H + dp * 16) * 2);
                mma_f16(o[2 * dp + 0], a0, a1, a2, a3, b0, b1);
                mma_f16(o[2 * dp + 1], a0, a1, a2, a3, b2, b3);
            }
        }
    }

    const int arow = wid * 16 + (lane >> 2);
    #pragma unroll
    for (int half = 0; half < 2; half++) {
        float inv = 1.0f / l_i[half];
        int srow = q0 + arow + half * 8;
        float* dst = out + ((size_t)b * SS + srow) * DD + h * DHH;
        #pragma unroll
        for (int nt = 0; nt < 8; nt++) {
            int d = nt * 8 + 2 * tig;
            float2 v = make_float2(o[nt][half * 2] * inv, o[nt][half * 2 + 1] * inv);
            *(float2*)(dst + d) = v;
        }
    }
}

// ---------------------------------------------------------------------------
extern "C" void kernel_launch(void* const* d_in, const int* in_sizes, int n_in,
                              void* d_out, int out_size)
{
    const float* X  = (const float*)d_in[0];
    const float* Wq = (const float*)d_in[1];
    const float* bq = (const float*)d_in[2];
    const float* Wk = (const float*)d_in[3];
    const float* bk = (const float*)d_in[4];
    const float* Wv = (const float*)d_in[5];
    const float* bv = (const float*)d_in[6];
    float* out = (float*)d_out;

    dim3 g1(DD / 128, NROWS / 128, 3);   // (6, 128, 3)
    qkv_mma_kernel<<<g1, 256>>>(X, Wq, bq, Wk, bk, Wv, bv);

    dim3 g2(SS / 128, BB * HH);          // (8, 192)
    attn_mma_kernel<<<g2, 256>>>(out);
}